// round 4
// baseline (speedup 1.0000x reference)
#include <cuda_runtime.h>
#include <cuda_bf16.h>

#define BN   4
#define CIN  3
#define CO   64
#define HH   512
#define WW   512
#define SS   (HH*WW)        /* 262144 = 2^18 */
#define NC   (BN*CO)        /* 256 */
#define HR   448
#define MM   (HR*HR)        /* 200704 */
#define NCS  (NC*SS)        /* 67108864 */
#define NCM  (NC*MM)        /* 51380224 */
#define KB   65536          /* bins per channel (16-bit sortable key) */

// ---------------- static device scratch (no runtime allocation) ----------------
__device__ unsigned int g_hist_src[NC*KB];   // 64 MB -> becomes exclusive CDF
__device__ unsigned int g_hist_ref[NC*KB];   // 64 MB -> becomes exclusive CDF
__device__ float        g_ref_sorted[NCM];   // 205 MB sorted ref values (f32)
__device__ double       g_accum[3];          // content, style, hist sums
__device__ float        g_gram[BN*CO*CO];

// ---------------- helpers ----------------
__device__ __forceinline__ unsigned int f2s(float x) {
    unsigned int u = __float_as_uint(x);
    return (u & 0x80000000u) ? ~u : (u | 0x80000000u);
}
__device__ __forceinline__ float s2f(unsigned int k) {
    unsigned int u = (k & 0x80000000u) ? (k ^ 0x80000000u) : ~k;
    return __uint_as_float(u);
}
// reconstruct float from 16-bit key (midpoint of bucket)
__device__ __forceinline__ float key2f(unsigned int k16) {
    return s2f((k16 << 16) | 0x8000u);
}

__device__ __forceinline__ void block_add(double v, double* target) {
    __shared__ double sh[8];
    int tid  = threadIdx.x + threadIdx.y * blockDim.x;
    int lane = tid & 31, wid = tid >> 5;
    int nwarps = (blockDim.x * blockDim.y + 31) >> 5;
    #pragma unroll
    for (int o = 16; o > 0; o >>= 1) v += __shfl_down_sync(0xffffffffu, v, o);
    if (lane == 0) sh[wid] = v;
    __syncthreads();
    if (wid == 0) {
        v = (lane < nwarps) ? sh[lane] : 0.0;
        #pragma unroll
        for (int o = 4; o > 0; o >>= 1) v += __shfl_down_sync(0xffffffffu, v, o);
        if (lane == 0) atomicAdd(target, v);
    }
}

// ---------------- init ----------------
__global__ void init_kernel() {
    int i = blockIdx.x * 256 + threadIdx.x;
    if (i < 3) g_accum[i] = 0.0;
    if (i < BN*CO*CO) g_gram[i] = 0.0f;
}

// ------ conv + bias + relu + content-loss + src histogram (fused) ------
__global__ void conv_kernel(const float* __restrict__ img, const float* __restrict__ w,
                            const float* __restrict__ b,   const float* __restrict__ ct,
                            float* __restrict__ out) {
    __shared__ float sin[3][10][34];
    __shared__ float sw[27][64];
    __shared__ float sb[64];
    const int n  = blockIdx.z;
    const int x0 = blockIdx.x * 32;
    const int y0 = blockIdx.y * 8;
    const int tid = threadIdx.y * 32 + threadIdx.x;

    for (int i = tid; i < 1728; i += 256) { int co = i / 27, tap = i % 27; sw[tap][co] = w[i]; }
    if (tid < 64) sb[tid] = b[tid];

    const float mean[3] = {0.485f, 0.456f, 0.406f};
    const float istd[3] = {1.f/0.229f, 1.f/0.224f, 1.f/0.225f};
    #pragma unroll
    for (int c = 0; c < 3; c++) {
        for (int i = tid; i < 340; i += 256) {
            int r = i / 34, cc = i % 34;
            int gy = y0 + r - 1, gx = x0 + cc - 1;
            float v = 0.f;
            if (gy >= 0 && gy < HH && gx >= 0 && gx < WW)
                v = (img[((n*3 + c)*HH + gy)*WW + gx] - mean[c]) * istd[c];
            sin[c][r][cc] = v;
        }
    }
    __syncthreads();

    const int px = threadIdx.x, py = threadIdx.y;
    float v[27];
    #pragma unroll
    for (int c = 0; c < 3; c++)
        #pragma unroll
        for (int ky = 0; ky < 3; ky++)
            #pragma unroll
            for (int kx = 0; kx < 3; kx++)
                v[c*9 + ky*3 + kx] = sin[c][py + ky][px + kx];

    const int y = y0 + py, x = x0 + px;
    double dsum = 0.0;
    #pragma unroll
    for (int cb = 0; cb < 64; cb += 16) {
        float acc[16];
        #pragma unroll
        for (int j = 0; j < 16; j++) acc[j] = sb[cb + j];
        #pragma unroll
        for (int t2 = 0; t2 < 27; t2++) {
            float vv = v[t2];
            #pragma unroll
            for (int j = 0; j < 16; j++) acc[j] = fmaf(vv, sw[t2][cb + j], acc[j]);
        }
        #pragma unroll
        for (int j = 0; j < 16; j++) {
            float f = acc[j] > 0.f ? acc[j] : 0.f;
            unsigned int ch = (unsigned int)(n*64 + cb + j);
            unsigned int oi = ch * SS + (unsigned int)y * WW + x;
            out[oi] = f;
            float d = f - ct[oi];
            dsum += (double)d * (double)d;
            // histogram: aggregate the (very common) exact-zero bin per warp
            unsigned int m = __ballot_sync(0xffffffffu, f == 0.f);
            if (f == 0.f) {
                if (threadIdx.x == (unsigned)(__ffs(m) - 1))
                    atomicAdd(&g_hist_src[ch * KB + 0x8000u], (unsigned int)__popc(m));
            } else {
                atomicAdd(&g_hist_src[ch * KB + (f2s(f) >> 16)], 1u);
            }
        }
    }
    block_add(dsum, &g_accum[0]);
}

// ---------------- ref histogram ----------------
__global__ void ref_hist_kernel(const float4* __restrict__ vals, unsigned int n4) {
    unsigned int t = blockIdx.x * 256 + threadIdx.x;
    if (t >= n4) return;
    float4 v = vals[t];
    unsigned int base = t * 4u;
    unsigned int ch = base / (unsigned int)MM;   // MM divisible by 4: no straddle
    unsigned int* h = &g_hist_ref[ch * KB];
    atomicAdd(&h[f2s(v.x) >> 16], 1u);
    atomicAdd(&h[f2s(v.y) >> 16], 1u);
    atomicAdd(&h[f2s(v.z) >> 16], 1u);
    atomicAdd(&h[f2s(v.w) >> 16], 1u);
}

// ---------------- per-channel exclusive scan over KB bins (in place) ----------------
__global__ void scan_kernel(unsigned int* __restrict__ hist) {
    unsigned int* h = hist + (size_t)blockIdx.x * KB;
    const int tid = threadIdx.x;         // 1024 threads
    const int lane = tid & 31, wid = tid >> 5;
    __shared__ unsigned int wsum[32];
    __shared__ unsigned int btot;
    unsigned int carry = 0;
    #pragma unroll
    for (int tile = 0; tile < 4; tile++) {
        const int base = tile * 16384 + tid * 16;
        uint4 a0 = *(uint4*)&h[base + 0];
        uint4 a1 = *(uint4*)&h[base + 4];
        uint4 a2 = *(uint4*)&h[base + 8];
        uint4 a3 = *(uint4*)&h[base + 12];
        unsigned int e[16] = {a0.x,a0.y,a0.z,a0.w, a1.x,a1.y,a1.z,a1.w,
                              a2.x,a2.y,a2.z,a2.w, a3.x,a3.y,a3.z,a3.w};
        unsigned int tsum = 0;
        #pragma unroll
        for (int i = 0; i < 16; i++) tsum += e[i];
        // warp inclusive scan of thread sums
        unsigned int inc = tsum;
        #pragma unroll
        for (int o = 1; o < 32; o <<= 1) {
            unsigned int nv = __shfl_up_sync(0xffffffffu, inc, o);
            if (lane >= o) inc += nv;
        }
        if (lane == 31) wsum[wid] = inc;
        __syncthreads();
        if (wid == 0) {
            unsigned int v0 = wsum[lane];
            unsigned int inc2 = v0;
            #pragma unroll
            for (int o = 1; o < 32; o <<= 1) {
                unsigned int nv = __shfl_up_sync(0xffffffffu, inc2, o);
                if (lane >= o) inc2 += nv;
            }
            wsum[lane] = inc2 - v0;          // exclusive warp prefix
            if (lane == 31) btot = inc2;     // tile total
        }
        __syncthreads();
        unsigned int run = carry + wsum[wid] + (inc - tsum);
        unsigned int o_[16];
        #pragma unroll
        for (int i = 0; i < 16; i++) { o_[i] = run; run += e[i]; }
        *(uint4*)&h[base + 0]  = make_uint4(o_[0], o_[1], o_[2], o_[3]);
        *(uint4*)&h[base + 4]  = make_uint4(o_[4], o_[5], o_[6], o_[7]);
        *(uint4*)&h[base + 8]  = make_uint4(o_[8], o_[9], o_[10], o_[11]);
        *(uint4*)&h[base + 12] = make_uint4(o_[12], o_[13], o_[14], o_[15]);
        carry += btot;
        __syncthreads();
    }
}

// ------- counting-sort writeout of sorted ref (f32 values) -------
__global__ void ref_writeout_kernel() {
    const int ch  = blockIdx.y;
    const int lane = threadIdx.x & 31, wid = threadIdx.x >> 5;
    const int b0 = blockIdx.x * 256 + wid * 32;
    const unsigned int* __restrict__ cum = &g_hist_ref[(size_t)ch * KB];
    float* __restrict__ outp = &g_ref_sorted[(size_t)ch * MM];
    const int b = b0 + lane;
    unsigned int p0v = cum[b];
    unsigned int p1v = (b == KB - 1) ? (unsigned int)MM : cum[b + 1];
    #pragma unroll 4
    for (int k = 0; k < 32; k++) {
        unsigned int p0 = __shfl_sync(0xffffffffu, p0v, k);
        unsigned int p1 = __shfl_sync(0xffffffffu, p1v, k);
        if (p1 > p0) {
            float v = key2f((unsigned int)(b0 + k));
            for (unsigned int p = p0 + lane; p < p1; p += 32) outp[p] = v;
        }
    }
}

// ------- hist loss: walk src bins, lerp ref quantiles, accumulate -------
__global__ void hist_loss_kernel() {
    const int ch  = blockIdx.y;
    const int lane = threadIdx.x & 31, wid = threadIdx.x >> 5;
    const int b0 = blockIdx.x * 256 + wid * 32;
    const unsigned int* __restrict__ cum = &g_hist_src[(size_t)ch * KB];
    const float* __restrict__ refq = &g_ref_sorted[(size_t)ch * MM];
    const float step = (float)(MM - 1) / (float)(SS - 1);
    const int b = b0 + lane;
    unsigned int p0v = cum[b];
    unsigned int p1v = (b == KB - 1) ? (unsigned int)SS : cum[b + 1];
    double acc = 0.0;
    for (int k = 0; k < 32; k++) {
        unsigned int p0 = __shfl_sync(0xffffffffu, p0v, k);
        unsigned int p1 = __shfl_sync(0xffffffffu, p1v, k);
        if (p1 > p0) {
            float v = key2f((unsigned int)(b0 + k));
            for (unsigned int p = p0 + lane; p < p1; p += 32) {
                float pos = step * (float)p;
                int lo = (int)floorf(pos);
                int hi = (int)ceilf(pos);
                if (lo > MM - 1) lo = MM - 1;
                if (hi > MM - 1) hi = MM - 1;
                float w   = pos - (float)lo;
                float r   = refq[lo] * (1.0f - w) + refq[hi] * w;
                float d   = v - r;
                acc += (double)d * (double)d;
            }
        }
    }
    block_add(acc, &g_accum[2]);
}

// ---------------- gram: per-batch F F^T, smem-tiled ----------------
#define GK 4096
#define GC 128
__global__ void gram_kernel(const float* __restrict__ feat) {
    __shared__ float tile[GC][68];
    const int n = blockIdx.y;
    const int base = blockIdx.x * GK;
    const int tid = threadIdx.x;
    const int r0 = (tid / 16) * 4, c0 = (tid % 16) * 4;
    float acc[4][4] = {};
    for (int cb = 0; cb < GK; cb += GC) {
        __syncthreads();
        #pragma unroll
        for (int it = 0; it < 32; it++) {
            int li = it * 256 + tid;
            int ch = li >> 7, k = li & 127;
            tile[k][ch] = feat[(unsigned int)(n*64 + ch) * SS + base + cb + k];
        }
        __syncthreads();
        #pragma unroll 4
        for (int k = 0; k < GC; k++) {
            float4 a  = *(const float4*)&tile[k][r0];
            float4 bq = *(const float4*)&tile[k][c0];
            acc[0][0] = fmaf(a.x, bq.x, acc[0][0]); acc[0][1] = fmaf(a.x, bq.y, acc[0][1]);
            acc[0][2] = fmaf(a.x, bq.z, acc[0][2]); acc[0][3] = fmaf(a.x, bq.w, acc[0][3]);
            acc[1][0] = fmaf(a.y, bq.x, acc[1][0]); acc[1][1] = fmaf(a.y, bq.y, acc[1][1]);
            acc[1][2] = fmaf(a.y, bq.z, acc[1][2]); acc[1][3] = fmaf(a.y, bq.w, acc[1][3]);
            acc[2][0] = fmaf(a.z, bq.x, acc[2][0]); acc[2][1] = fmaf(a.z, bq.y, acc[2][1]);
            acc[2][2] = fmaf(a.z, bq.z, acc[2][2]); acc[2][3] = fmaf(a.z, bq.w, acc[2][3]);
            acc[3][0] = fmaf(a.w, bq.x, acc[3][0]); acc[3][1] = fmaf(a.w, bq.y, acc[3][1]);
            acc[3][2] = fmaf(a.w, bq.z, acc[3][2]); acc[3][3] = fmaf(a.w, bq.w, acc[3][3]);
        }
    }
    #pragma unroll
    for (int i = 0; i < 4; i++)
        #pragma unroll
        for (int j = 0; j < 4; j++)
            atomicAdd(&g_gram[n*4096 + (r0 + i)*64 + c0 + j], acc[i][j]);
}

// ---------------- style loss ----------------
__global__ void style_kernel(const float* __restrict__ tgt) {
    int i = blockIdx.x * 256 + threadIdx.x;
    double d = 0.0;
    if (i < BN*CO*CO) {
        float g = g_gram[i] * (1.0f / ((float)CO * HH * WW));
        float df = g - tgt[i];
        d = (double)df * (double)df;
    }
    block_add(d, &g_accum[1]);
}

// ---------------- finalize ----------------
__global__ void finalize_kernel(float* __restrict__ out) {
    if (threadIdx.x == 0) {
        out[NCS + 0] = (float)(g_accum[0] / (double)NCS);
        out[NCS + 1] = (float)(g_accum[1] / (double)(BN*CO*CO));
        out[NCS + 2] = (float)(g_accum[2] / (double)NCS);
    }
}

// ---------------- launch ----------------
extern "C" void kernel_launch(void* const* d_in, const int* in_sizes, int n_in,
                              void* d_out, int out_size) {
    const float* img  = (const float*)d_in[0];
    const float* w    = (const float*)d_in[1];
    const float* b    = (const float*)d_in[2];
    const float* ct   = (const float*)d_in[3];
    const float* stg  = (const float*)d_in[4];
    const float* hist = (const float*)d_in[5];
    float* out = (float*)d_out;

    void *p_hs, *p_hr;
    cudaGetSymbolAddress(&p_hs, g_hist_src);
    cudaGetSymbolAddress(&p_hr, g_hist_ref);

    cudaMemsetAsync(p_hs, 0, (size_t)NC * KB * 4, 0);
    cudaMemsetAsync(p_hr, 0, (size_t)NC * KB * 4, 0);
    init_kernel<<<64, 256>>>();

    dim3 cgrid(WW/32, HH/8, BN), cblk(32, 8);
    conv_kernel<<<cgrid, cblk>>>(img, w, b, ct, out);

    ref_hist_kernel<<<(NCM/4 + 255)/256, 256>>>((const float4*)hist, NCM/4);

    scan_kernel<<<NC, 1024>>>((unsigned int*)p_hs);
    scan_kernel<<<NC, 1024>>>((unsigned int*)p_hr);

    ref_writeout_kernel<<<dim3(KB/256, NC), 256>>>();

    gram_kernel<<<dim3(SS/GK, BN), 256>>>(out);
    style_kernel<<<(BN*CO*CO + 255)/256, 256>>>(stg);

    hist_loss_kernel<<<dim3(KB/256, NC), 256>>>();

    finalize_kernel<<<1, 32>>>(out);
    (void)in_sizes; (void)n_in; (void)out_size;
}

// round 5
// speedup vs baseline: 1.2799x; 1.2799x over previous
#include <cuda_runtime.h>
#include <cuda_bf16.h>

#define BN   4
#define CIN  3
#define CO   64
#define HH   512
#define WW   512
#define SS   (HH*WW)        /* 262144 = 2^18 */
#define NC   (BN*CO)        /* 256 */
#define HR   448
#define MM   (HR*HR)        /* 200704 */
#define NCS  (NC*SS)        /* 67108864 */
#define NCM  (NC*MM)        /* 51380224 */
#define KB   65536          /* bins per channel (16-bit sortable key) */

// ---------------- static device scratch (no runtime allocation) ----------------
__device__ unsigned int g_hist_src[NC*KB];   // 64 MB -> becomes exclusive CDF
__device__ unsigned int g_hist_ref[NC*KB];   // 64 MB -> becomes exclusive CDF
__device__ float        g_ref_sorted[NCM];   // 205 MB sorted ref values (f32)
__device__ double       g_accum[3];          // content, style, hist sums
__device__ float        g_gram[BN*CO*CO];

// ---------------- helpers ----------------
__device__ __forceinline__ unsigned int f2s(float x) {
    unsigned int u = __float_as_uint(x);
    return (u & 0x80000000u) ? ~u : (u | 0x80000000u);
}
__device__ __forceinline__ float s2f(unsigned int k) {
    unsigned int u = (k & 0x80000000u) ? (k ^ 0x80000000u) : ~k;
    return __uint_as_float(u);
}
// reconstruct float from 16-bit key (midpoint of bucket)
__device__ __forceinline__ float key2f(unsigned int k16) {
    return s2f((k16 << 16) | 0x8000u);
}

__device__ __forceinline__ void block_add(double v, double* target) {
    __shared__ double sh[8];
    int tid  = threadIdx.x + threadIdx.y * blockDim.x;
    int lane = tid & 31, wid = tid >> 5;
    int nwarps = (blockDim.x * blockDim.y + 31) >> 5;
    #pragma unroll
    for (int o = 16; o > 0; o >>= 1) v += __shfl_down_sync(0xffffffffu, v, o);
    if (lane == 0) sh[wid] = v;
    __syncthreads();
    if (wid == 0) {
        v = (lane < nwarps) ? sh[lane] : 0.0;
        #pragma unroll
        for (int o = 4; o > 0; o >>= 1) v += __shfl_down_sync(0xffffffffu, v, o);
        if (lane == 0) atomicAdd(target, v);
    }
}

// ---------------- init ----------------
__global__ void init_kernel() {
    int i = blockIdx.x * 256 + threadIdx.x;
    if (i < 3) g_accum[i] = 0.0;
    if (i < BN*CO*CO) g_gram[i] = 0.0f;
}

// ------ conv + bias + relu + content-loss (fused) ------
__global__ void conv_kernel(const float* __restrict__ img, const float* __restrict__ w,
                            const float* __restrict__ b,   const float* __restrict__ ct,
                            float* __restrict__ out) {
    __shared__ float sin[3][10][34];
    __shared__ float sw[27][64];
    __shared__ float sb[64];
    const int n  = blockIdx.z;
    const int x0 = blockIdx.x * 32;
    const int y0 = blockIdx.y * 8;
    const int tid = threadIdx.y * 32 + threadIdx.x;

    for (int i = tid; i < 1728; i += 256) { int co = i / 27, tap = i % 27; sw[tap][co] = w[i]; }
    if (tid < 64) sb[tid] = b[tid];

    const float mean[3] = {0.485f, 0.456f, 0.406f};
    const float istd[3] = {1.f/0.229f, 1.f/0.224f, 1.f/0.225f};
    #pragma unroll
    for (int c = 0; c < 3; c++) {
        for (int i = tid; i < 340; i += 256) {
            int r = i / 34, cc = i % 34;
            int gy = y0 + r - 1, gx = x0 + cc - 1;
            float v = 0.f;
            if (gy >= 0 && gy < HH && gx >= 0 && gx < WW)
                v = (img[((n*3 + c)*HH + gy)*WW + gx] - mean[c]) * istd[c];
            sin[c][r][cc] = v;
        }
    }
    __syncthreads();

    const int px = threadIdx.x, py = threadIdx.y;
    float v[27];
    #pragma unroll
    for (int c = 0; c < 3; c++)
        #pragma unroll
        for (int ky = 0; ky < 3; ky++)
            #pragma unroll
            for (int kx = 0; kx < 3; kx++)
                v[c*9 + ky*3 + kx] = sin[c][py + ky][px + kx];

    const int y = y0 + py, x = x0 + px;
    double dsum = 0.0;
    #pragma unroll
    for (int cb = 0; cb < 64; cb += 16) {
        float acc[16];
        #pragma unroll
        for (int j = 0; j < 16; j++) acc[j] = sb[cb + j];
        #pragma unroll
        for (int t2 = 0; t2 < 27; t2++) {
            float vv = v[t2];
            #pragma unroll
            for (int j = 0; j < 16; j++) acc[j] = fmaf(vv, sw[t2][cb + j], acc[j]);
        }
        #pragma unroll
        for (int j = 0; j < 16; j++) {
            float f = acc[j] > 0.f ? acc[j] : 0.f;
            unsigned int ch = (unsigned int)(n*64 + cb + j);
            unsigned int oi = ch * SS + (unsigned int)y * WW + x;
            out[oi] = f;
            float d = f - ct[oi];
            dsum += (double)d * (double)d;
        }
    }
    block_add(dsum, &g_accum[0]);
}

// ------ per-channel histogram of feat: 1 block/channel, smem-privatized ------
// 65536 bins as 16-bit counters packed 2-per-u32 (128 KB dynamic smem).
// Exact zeros (massive bin, would overflow 16-bit) counted in registers.
__global__ void __launch_bounds__(1024) src_hist_kernel(const float4* __restrict__ feat) {
    extern __shared__ unsigned int sh[];  // KB/2 = 32768 words
    __shared__ unsigned int zwarp[32];
    __shared__ unsigned int ztot;
    const int ch  = blockIdx.x;
    const int tid = threadIdx.x;
    for (int i = tid; i < KB/2; i += 1024) sh[i] = 0;
    __syncthreads();

    const float4* p = feat + (size_t)ch * (SS/4);
    unsigned int zc = 0;
    for (int i = tid; i < SS/4; i += 1024) {
        float4 v = p[i];
        float e[4] = {v.x, v.y, v.z, v.w};
        #pragma unroll
        for (int j = 0; j < 4; j++) {
            float f = e[j];
            if (f == 0.f) { zc++; }
            else {
                unsigned int k = f2s(f) >> 16;
                atomicAdd(&sh[k >> 1], 1u << ((k & 1) * 16));
            }
        }
    }
    // reduce zero count
    int lane = tid & 31, wid = tid >> 5;
    #pragma unroll
    for (int o = 16; o > 0; o >>= 1) zc += __shfl_down_sync(0xffffffffu, zc, o);
    if (lane == 0) zwarp[wid] = zc;
    __syncthreads();
    if (tid == 0) {
        unsigned int s = 0;
        #pragma unroll
        for (int i = 0; i < 32; i++) s += zwarp[i];
        ztot = s;
    }
    __syncthreads();

    unsigned int* g = &g_hist_src[(size_t)ch * KB];
    for (int i = tid; i < KB/2; i += 1024) {
        unsigned int wv = sh[i];
        unsigned int lo = wv & 0xffffu;
        if (i == (0x8000 >> 1)) lo += ztot;   // zero bin = key 0x8000 (even -> low half)
        g[2*i]     = lo;
        g[2*i + 1] = wv >> 16;
    }
}

// ------ per-channel histogram of ref target (no zero special-case needed) ------
__global__ void __launch_bounds__(1024) ref_hist_kernel(const float4* __restrict__ vals) {
    extern __shared__ unsigned int sh[];
    const int ch  = blockIdx.x;
    const int tid = threadIdx.x;
    for (int i = tid; i < KB/2; i += 1024) sh[i] = 0;
    __syncthreads();

    const float4* p = vals + (size_t)ch * (MM/4);
    for (int i = tid; i < MM/4; i += 1024) {
        float4 v = p[i];
        float e[4] = {v.x, v.y, v.z, v.w};
        #pragma unroll
        for (int j = 0; j < 4; j++) {
            unsigned int k = f2s(e[j]) >> 16;
            atomicAdd(&sh[k >> 1], 1u << ((k & 1) * 16));
        }
    }
    __syncthreads();

    unsigned int* g = &g_hist_ref[(size_t)ch * KB];
    for (int i = tid; i < KB/2; i += 1024) {
        unsigned int wv = sh[i];
        g[2*i]     = wv & 0xffffu;
        g[2*i + 1] = wv >> 16;
    }
}

// ---------------- per-channel exclusive scan over KB bins (in place) ----------------
__global__ void scan_kernel(unsigned int* __restrict__ hist) {
    unsigned int* h = hist + (size_t)blockIdx.x * KB;
    const int tid = threadIdx.x;         // 1024 threads
    const int lane = tid & 31, wid = tid >> 5;
    __shared__ unsigned int wsum[32];
    __shared__ unsigned int btot;
    unsigned int carry = 0;
    #pragma unroll
    for (int tile = 0; tile < 4; tile++) {
        const int base = tile * 16384 + tid * 16;
        uint4 a0 = *(uint4*)&h[base + 0];
        uint4 a1 = *(uint4*)&h[base + 4];
        uint4 a2 = *(uint4*)&h[base + 8];
        uint4 a3 = *(uint4*)&h[base + 12];
        unsigned int e[16] = {a0.x,a0.y,a0.z,a0.w, a1.x,a1.y,a1.z,a1.w,
                              a2.x,a2.y,a2.z,a2.w, a3.x,a3.y,a3.z,a3.w};
        unsigned int tsum = 0;
        #pragma unroll
        for (int i = 0; i < 16; i++) tsum += e[i];
        unsigned int inc = tsum;
        #pragma unroll
        for (int o = 1; o < 32; o <<= 1) {
            unsigned int nv = __shfl_up_sync(0xffffffffu, inc, o);
            if (lane >= o) inc += nv;
        }
        if (lane == 31) wsum[wid] = inc;
        __syncthreads();
        if (wid == 0) {
            unsigned int v0 = wsum[lane];
            unsigned int inc2 = v0;
            #pragma unroll
            for (int o = 1; o < 32; o <<= 1) {
                unsigned int nv = __shfl_up_sync(0xffffffffu, inc2, o);
                if (lane >= o) inc2 += nv;
            }
            wsum[lane] = inc2 - v0;
            if (lane == 31) btot = inc2;
        }
        __syncthreads();
        unsigned int run = carry + wsum[wid] + (inc - tsum);
        unsigned int o_[16];
        #pragma unroll
        for (int i = 0; i < 16; i++) { o_[i] = run; run += e[i]; }
        *(uint4*)&h[base + 0]  = make_uint4(o_[0], o_[1], o_[2], o_[3]);
        *(uint4*)&h[base + 4]  = make_uint4(o_[4], o_[5], o_[6], o_[7]);
        *(uint4*)&h[base + 8]  = make_uint4(o_[8], o_[9], o_[10], o_[11]);
        *(uint4*)&h[base + 12] = make_uint4(o_[12], o_[13], o_[14], o_[15]);
        carry += btot;
        __syncthreads();
    }
}

// ------- counting-sort writeout of sorted ref (f32 values) -------
__global__ void ref_writeout_kernel() {
    const int ch  = blockIdx.y;
    const int lane = threadIdx.x & 31, wid = threadIdx.x >> 5;
    const int b0 = blockIdx.x * 256 + wid * 32;
    const unsigned int* __restrict__ cum = &g_hist_ref[(size_t)ch * KB];
    float* __restrict__ outp = &g_ref_sorted[(size_t)ch * MM];
    const int b = b0 + lane;
    unsigned int p0v = cum[b];
    unsigned int p1v = (b == KB - 1) ? (unsigned int)MM : cum[b + 1];
    #pragma unroll 4
    for (int k = 0; k < 32; k++) {
        unsigned int p0 = __shfl_sync(0xffffffffu, p0v, k);
        unsigned int p1 = __shfl_sync(0xffffffffu, p1v, k);
        if (p1 > p0) {
            float v = key2f((unsigned int)(b0 + k));
            for (unsigned int p = p0 + lane; p < p1; p += 32) outp[p] = v;
        }
    }
}

// ------- hist loss: walk src bins, lerp ref quantiles, accumulate -------
__global__ void hist_loss_kernel() {
    const int ch  = blockIdx.y;
    const int lane = threadIdx.x & 31, wid = threadIdx.x >> 5;
    const int b0 = blockIdx.x * 256 + wid * 32;
    const unsigned int* __restrict__ cum = &g_hist_src[(size_t)ch * KB];
    const float* __restrict__ refq = &g_ref_sorted[(size_t)ch * MM];
    const float step = (float)(MM - 1) / (float)(SS - 1);
    const int b = b0 + lane;
    unsigned int p0v = cum[b];
    unsigned int p1v = (b == KB - 1) ? (unsigned int)SS : cum[b + 1];
    double acc = 0.0;
    for (int k = 0; k < 32; k++) {
        unsigned int p0 = __shfl_sync(0xffffffffu, p0v, k);
        unsigned int p1 = __shfl_sync(0xffffffffu, p1v, k);
        if (p1 > p0) {
            float v = key2f((unsigned int)(b0 + k));
            for (unsigned int p = p0 + lane; p < p1; p += 32) {
                float pos = step * (float)p;
                int lo = (int)floorf(pos);
                int hi = (int)ceilf(pos);
                if (lo > MM - 1) lo = MM - 1;
                if (hi > MM - 1) hi = MM - 1;
                float w   = pos - (float)lo;
                float r   = refq[lo] * (1.0f - w) + refq[hi] * w;
                float d   = v - r;
                acc += (double)d * (double)d;
            }
        }
    }
    block_add(acc, &g_accum[2]);
}

// ---------------- gram: per-batch F F^T, smem-tiled ----------------
#define GK 4096
#define GC 128
__global__ void gram_kernel(const float* __restrict__ feat) {
    __shared__ float tile[GC][68];
    const int n = blockIdx.y;
    const int base = blockIdx.x * GK;
    const int tid = threadIdx.x;
    const int r0 = (tid / 16) * 4, c0 = (tid % 16) * 4;
    float acc[4][4] = {};
    for (int cb = 0; cb < GK; cb += GC) {
        __syncthreads();
        #pragma unroll
        for (int it = 0; it < 32; it++) {
            int li = it * 256 + tid;
            int ch = li >> 7, k = li & 127;
            tile[k][ch] = feat[(unsigned int)(n*64 + ch) * SS + base + cb + k];
        }
        __syncthreads();
        #pragma unroll 4
        for (int k = 0; k < GC; k++) {
            float4 a  = *(const float4*)&tile[k][r0];
            float4 bq = *(const float4*)&tile[k][c0];
            acc[0][0] = fmaf(a.x, bq.x, acc[0][0]); acc[0][1] = fmaf(a.x, bq.y, acc[0][1]);
            acc[0][2] = fmaf(a.x, bq.z, acc[0][2]); acc[0][3] = fmaf(a.x, bq.w, acc[0][3]);
            acc[1][0] = fmaf(a.y, bq.x, acc[1][0]); acc[1][1] = fmaf(a.y, bq.y, acc[1][1]);
            acc[1][2] = fmaf(a.y, bq.z, acc[1][2]); acc[1][3] = fmaf(a.y, bq.w, acc[1][3]);
            acc[2][0] = fmaf(a.z, bq.x, acc[2][0]); acc[2][1] = fmaf(a.z, bq.y, acc[2][1]);
            acc[2][2] = fmaf(a.z, bq.z, acc[2][2]); acc[2][3] = fmaf(a.z, bq.w, acc[2][3]);
            acc[3][0] = fmaf(a.w, bq.x, acc[3][0]); acc[3][1] = fmaf(a.w, bq.y, acc[3][1]);
            acc[3][2] = fmaf(a.w, bq.z, acc[3][2]); acc[3][3] = fmaf(a.w, bq.w, acc[3][3]);
        }
    }
    #pragma unroll
    for (int i = 0; i < 4; i++)
        #pragma unroll
        for (int j = 0; j < 4; j++)
            atomicAdd(&g_gram[n*4096 + (r0 + i)*64 + c0 + j], acc[i][j]);
}

// ---------------- style loss ----------------
__global__ void style_kernel(const float* __restrict__ tgt) {
    int i = blockIdx.x * 256 + threadIdx.x;
    double d = 0.0;
    if (i < BN*CO*CO) {
        float g = g_gram[i] * (1.0f / ((float)CO * HH * WW));
        float df = g - tgt[i];
        d = (double)df * (double)df;
    }
    block_add(d, &g_accum[1]);
}

// ---------------- finalize ----------------
__global__ void finalize_kernel(float* __restrict__ out) {
    if (threadIdx.x == 0) {
        out[NCS + 0] = (float)(g_accum[0] / (double)NCS);
        out[NCS + 1] = (float)(g_accum[1] / (double)(BN*CO*CO));
        out[NCS + 2] = (float)(g_accum[2] / (double)NCS);
    }
}

// ---------------- launch ----------------
extern "C" void kernel_launch(void* const* d_in, const int* in_sizes, int n_in,
                              void* d_out, int out_size) {
    const float* img  = (const float*)d_in[0];
    const float* w    = (const float*)d_in[1];
    const float* b    = (const float*)d_in[2];
    const float* ct   = (const float*)d_in[3];
    const float* stg  = (const float*)d_in[4];
    const float* hist = (const float*)d_in[5];
    float* out = (float*)d_out;

    void *p_hs, *p_hr;
    cudaGetSymbolAddress(&p_hs, g_hist_src);
    cudaGetSymbolAddress(&p_hr, g_hist_ref);

    static int smem_set = 0;
    if (!smem_set) {
        cudaFuncSetAttribute(src_hist_kernel, cudaFuncAttributeMaxDynamicSharedMemorySize, 131072);
        cudaFuncSetAttribute(ref_hist_kernel, cudaFuncAttributeMaxDynamicSharedMemorySize, 131072);
        smem_set = 1;
    }

    init_kernel<<<64, 256>>>();

    dim3 cgrid(WW/32, HH/8, BN), cblk(32, 8);
    conv_kernel<<<cgrid, cblk>>>(img, w, b, ct, out);

    src_hist_kernel<<<NC, 1024, 131072>>>((const float4*)out);
    ref_hist_kernel<<<NC, 1024, 131072>>>((const float4*)hist);

    scan_kernel<<<NC, 1024>>>((unsigned int*)p_hs);
    scan_kernel<<<NC, 1024>>>((unsigned int*)p_hr);

    ref_writeout_kernel<<<dim3(KB/256, NC), 256>>>();

    gram_kernel<<<dim3(SS/GK, BN), 256>>>(out);
    style_kernel<<<(BN*CO*CO + 255)/256, 256>>>(stg);

    hist_loss_kernel<<<dim3(KB/256, NC), 256>>>();

    finalize_kernel<<<1, 32>>>(out);
    (void)in_sizes; (void)n_in; (void)out_size;
}

// round 6
// speedup vs baseline: 2.7639x; 2.1595x over previous
#include <cuda_runtime.h>
#include <cuda_bf16.h>

#define BN   4
#define CIN  3
#define CO   64
#define HH   512
#define WW   512
#define SS   (HH*WW)        /* 262144 = 2^18 */
#define NC   (BN*CO)        /* 256 */
#define HR   448
#define MM   (HR*HR)        /* 200704 */
#define NCS  (NC*SS)        /* 67108864 */
#define NCM  (NC*MM)        /* 51380224 */
#define KB   65536          /* bins per channel (16-bit sortable key) */

// ---------------- static device scratch (no runtime allocation) ----------------
__device__ unsigned int g_hist_src[NC*KB];   // 64 MB -> becomes exclusive CDF
__device__ unsigned int g_hist_ref[NC*KB];   // 64 MB -> becomes exclusive CDF
__device__ float        g_src_sorted[NCS];   // 268 MB sorted src values (f32)
__device__ float        g_ref_sorted[NCM];   // 205 MB sorted ref values (f32)
__device__ double       g_accum[3];          // content, style, hist sums
__device__ float        g_gram[BN*CO*CO];

// ---------------- helpers ----------------
__device__ __forceinline__ unsigned int f2s(float x) {
    unsigned int u = __float_as_uint(x);
    return (u & 0x80000000u) ? ~u : (u | 0x80000000u);
}
__device__ __forceinline__ float s2f(unsigned int k) {
    unsigned int u = (k & 0x80000000u) ? (k ^ 0x80000000u) : ~k;
    return __uint_as_float(u);
}
// reconstruct float from 16-bit key (midpoint of bucket)
__device__ __forceinline__ float key2f(unsigned int k16) {
    return s2f((k16 << 16) | 0x8000u);
}

__device__ __forceinline__ void block_add(double v, double* target) {
    __shared__ double sh[8];
    int tid  = threadIdx.x + threadIdx.y * blockDim.x;
    int lane = tid & 31, wid = tid >> 5;
    int nwarps = (blockDim.x * blockDim.y + 31) >> 5;
    #pragma unroll
    for (int o = 16; o > 0; o >>= 1) v += __shfl_down_sync(0xffffffffu, v, o);
    if (lane == 0) sh[wid] = v;
    __syncthreads();
    if (wid == 0) {
        v = (lane < nwarps) ? sh[lane] : 0.0;
        #pragma unroll
        for (int o = 4; o > 0; o >>= 1) v += __shfl_down_sync(0xffffffffu, v, o);
        if (lane == 0) atomicAdd(target, v);
    }
}

// ---------------- init ----------------
__global__ void init_kernel() {
    int i = blockIdx.x * 256 + threadIdx.x;
    if (i < 3) g_accum[i] = 0.0;
    if (i < BN*CO*CO) g_gram[i] = 0.0f;
}

// ------ conv + bias + relu + content-loss (fused, float partial sums) ------
__global__ void conv_kernel(const float* __restrict__ img, const float* __restrict__ w,
                            const float* __restrict__ b,   const float* __restrict__ ct,
                            float* __restrict__ out) {
    __shared__ float sin[3][10][34];
    __shared__ float sw[27][64];
    __shared__ float sb[64];
    const int n  = blockIdx.z;
    const int x0 = blockIdx.x * 32;
    const int y0 = blockIdx.y * 8;
    const int tid = threadIdx.y * 32 + threadIdx.x;

    for (int i = tid; i < 1728; i += 256) { int co = i / 27, tap = i % 27; sw[tap][co] = w[i]; }
    if (tid < 64) sb[tid] = b[tid];

    const float mean[3] = {0.485f, 0.456f, 0.406f};
    const float istd[3] = {1.f/0.229f, 1.f/0.224f, 1.f/0.225f};
    #pragma unroll
    for (int c = 0; c < 3; c++) {
        for (int i = tid; i < 340; i += 256) {
            int r = i / 34, cc = i % 34;
            int gy = y0 + r - 1, gx = x0 + cc - 1;
            float v = 0.f;
            if (gy >= 0 && gy < HH && gx >= 0 && gx < WW)
                v = (img[((n*3 + c)*HH + gy)*WW + gx] - mean[c]) * istd[c];
            sin[c][r][cc] = v;
        }
    }
    __syncthreads();

    const int px = threadIdx.x, py = threadIdx.y;
    float v[27];
    #pragma unroll
    for (int c = 0; c < 3; c++)
        #pragma unroll
        for (int ky = 0; ky < 3; ky++)
            #pragma unroll
            for (int kx = 0; kx < 3; kx++)
                v[c*9 + ky*3 + kx] = sin[c][py + ky][px + kx];

    const int y = y0 + py, x = x0 + px;
    float fsum = 0.f;
    #pragma unroll
    for (int cb = 0; cb < 64; cb += 16) {
        float acc[16];
        #pragma unroll
        for (int j = 0; j < 16; j++) acc[j] = sb[cb + j];
        #pragma unroll
        for (int t2 = 0; t2 < 27; t2++) {
            float vv = v[t2];
            #pragma unroll
            for (int j = 0; j < 16; j++) acc[j] = fmaf(vv, sw[t2][cb + j], acc[j]);
        }
        #pragma unroll
        for (int j = 0; j < 16; j++) {
            float f = acc[j] > 0.f ? acc[j] : 0.f;
            unsigned int ch = (unsigned int)(n*64 + cb + j);
            unsigned int oi = ch * SS + (unsigned int)y * WW + x;
            out[oi] = f;
            float d = f - ct[oi];
            fsum = fmaf(d, d, fsum);
        }
    }
    block_add((double)fsum, &g_accum[0]);
}

// ------ per-channel histogram of feat: 1 block/channel, smem-privatized ------
__global__ void __launch_bounds__(1024) src_hist_kernel(const float4* __restrict__ feat) {
    extern __shared__ unsigned int sh[];  // KB/2 = 32768 words
    __shared__ unsigned int zwarp[32];
    __shared__ unsigned int ztot;
    const int ch  = blockIdx.x;
    const int tid = threadIdx.x;
    for (int i = tid; i < KB/2; i += 1024) sh[i] = 0;
    __syncthreads();

    const float4* p = feat + (size_t)ch * (SS/4);
    unsigned int zc = 0;
    for (int i = tid; i < SS/4; i += 1024) {
        float4 v = p[i];
        float e[4] = {v.x, v.y, v.z, v.w};
        #pragma unroll
        for (int j = 0; j < 4; j++) {
            float f = e[j];
            if (f == 0.f) { zc++; }
            else {
                unsigned int k = f2s(f) >> 16;
                atomicAdd(&sh[k >> 1], 1u << ((k & 1) * 16));
            }
        }
    }
    int lane = tid & 31, wid = tid >> 5;
    #pragma unroll
    for (int o = 16; o > 0; o >>= 1) zc += __shfl_down_sync(0xffffffffu, zc, o);
    if (lane == 0) zwarp[wid] = zc;
    __syncthreads();
    if (tid == 0) {
        unsigned int s = 0;
        #pragma unroll
        for (int i = 0; i < 32; i++) s += zwarp[i];
        ztot = s;
    }
    __syncthreads();

    unsigned int* g = &g_hist_src[(size_t)ch * KB];
    for (int i = tid; i < KB/2; i += 1024) {
        unsigned int wv = sh[i];
        unsigned int lo = wv & 0xffffu;
        if (i == (0x8000 >> 1)) lo += ztot;   // zero bin = key 0x8000
        g[2*i]     = lo;
        g[2*i + 1] = wv >> 16;
    }
}

// ------ per-channel histogram of ref target ------
__global__ void __launch_bounds__(1024) ref_hist_kernel(const float4* __restrict__ vals) {
    extern __shared__ unsigned int sh[];
    const int ch  = blockIdx.x;
    const int tid = threadIdx.x;
    for (int i = tid; i < KB/2; i += 1024) sh[i] = 0;
    __syncthreads();

    const float4* p = vals + (size_t)ch * (MM/4);
    for (int i = tid; i < MM/4; i += 1024) {
        float4 v = p[i];
        float e[4] = {v.x, v.y, v.z, v.w};
        #pragma unroll
        for (int j = 0; j < 4; j++) {
            unsigned int k = f2s(e[j]) >> 16;
            atomicAdd(&sh[k >> 1], 1u << ((k & 1) * 16));
        }
    }
    __syncthreads();

    unsigned int* g = &g_hist_ref[(size_t)ch * KB];
    for (int i = tid; i < KB/2; i += 1024) {
        unsigned int wv = sh[i];
        g[2*i]     = wv & 0xffffu;
        g[2*i + 1] = wv >> 16;
    }
}

// ---------------- per-channel exclusive scan over KB bins (in place) ----------------
__global__ void scan_kernel(unsigned int* __restrict__ hist) {
    unsigned int* h = hist + (size_t)blockIdx.x * KB;
    const int tid = threadIdx.x;         // 1024 threads
    const int lane = tid & 31, wid = tid >> 5;
    __shared__ unsigned int wsum[32];
    __shared__ unsigned int btot;
    unsigned int carry = 0;
    #pragma unroll
    for (int tile = 0; tile < 4; tile++) {
        const int base = tile * 16384 + tid * 16;
        uint4 a0 = *(uint4*)&h[base + 0];
        uint4 a1 = *(uint4*)&h[base + 4];
        uint4 a2 = *(uint4*)&h[base + 8];
        uint4 a3 = *(uint4*)&h[base + 12];
        unsigned int e[16] = {a0.x,a0.y,a0.z,a0.w, a1.x,a1.y,a1.z,a1.w,
                              a2.x,a2.y,a2.z,a2.w, a3.x,a3.y,a3.z,a3.w};
        unsigned int tsum = 0;
        #pragma unroll
        for (int i = 0; i < 16; i++) tsum += e[i];
        unsigned int inc = tsum;
        #pragma unroll
        for (int o = 1; o < 32; o <<= 1) {
            unsigned int nv = __shfl_up_sync(0xffffffffu, inc, o);
            if (lane >= o) inc += nv;
        }
        if (lane == 31) wsum[wid] = inc;
        __syncthreads();
        if (wid == 0) {
            unsigned int v0 = wsum[lane];
            unsigned int inc2 = v0;
            #pragma unroll
            for (int o = 1; o < 32; o <<= 1) {
                unsigned int nv = __shfl_up_sync(0xffffffffu, inc2, o);
                if (lane >= o) inc2 += nv;
            }
            wsum[lane] = inc2 - v0;
            if (lane == 31) btot = inc2;
        }
        __syncthreads();
        unsigned int run = carry + wsum[wid] + (inc - tsum);
        unsigned int o_[16];
        #pragma unroll
        for (int i = 0; i < 16; i++) { o_[i] = run; run += e[i]; }
        *(uint4*)&h[base + 0]  = make_uint4(o_[0], o_[1], o_[2], o_[3]);
        *(uint4*)&h[base + 4]  = make_uint4(o_[4], o_[5], o_[6], o_[7]);
        *(uint4*)&h[base + 8]  = make_uint4(o_[8], o_[9], o_[10], o_[11]);
        *(uint4*)&h[base + 12] = make_uint4(o_[12], o_[13], o_[14], o_[15]);
        carry += btot;
        __syncthreads();
    }
}

// ------- counting-sort writeout (store-only: imbalance-benign) -------
__global__ void writeout_kernel(const unsigned int* __restrict__ hist,
                                float* __restrict__ sorted, unsigned int seglen) {
    const int ch  = blockIdx.y;
    const int lane = threadIdx.x & 31, wid = threadIdx.x >> 5;
    const int b0 = blockIdx.x * 256 + wid * 32;
    const unsigned int* __restrict__ cum = hist + (size_t)ch * KB;
    float* __restrict__ outp = sorted + (size_t)ch * seglen;
    const int b = b0 + lane;
    unsigned int p0v = cum[b];
    unsigned int p1v = (b == KB - 1) ? seglen : cum[b + 1];
    for (int k = 0; k < 32; k++) {
        unsigned int p0 = __shfl_sync(0xffffffffu, p0v, k);
        unsigned int p1 = __shfl_sync(0xffffffffu, p1v, k);
        if (p1 > p0) {
            float v = key2f((unsigned int)(b0 + k));
            for (unsigned int p = p0 + lane; p < p1; p += 32) outp[p] = v;
        }
    }
}

// ------- hist loss: position-parallel streaming (balanced, coalesced) -------
__global__ void hist_loss_kernel() {
    const unsigned int t = blockIdx.x * 256u + threadIdx.x;     // one float4 per thread
    const unsigned int base = t * 4u;
    const unsigned int c = base >> 18;          // / SS
    const unsigned int i = base & (SS - 1);
    const float step = (float)(MM - 1) / (float)(SS - 1);
    float4 sv = *(const float4*)&g_src_sorted[base];
    const float* __restrict__ refq = &g_ref_sorted[(size_t)c * MM];
    float e[4] = {sv.x, sv.y, sv.z, sv.w};
    float fsum = 0.f;
    #pragma unroll
    for (int j = 0; j < 4; j++) {
        float pos = step * (float)(i + j);
        int lo = (int)pos;
        float w = pos - (float)lo;
        int hi = lo + (w > 0.f ? 1 : 0);
        if (hi > MM - 1) hi = MM - 1;
        float rlo = refq[lo];
        float rhi = refq[hi];
        float r   = rlo + (rhi - rlo) * w;
        // match reference lerp form: rlo*(1-w) + rhi*w
        r = rlo * (1.0f - w) + rhi * w;
        float d = e[j] - r;
        fsum = fmaf(d, d, fsum);
    }
    block_add((double)fsum, &g_accum[2]);
}

// ---------------- gram: per-batch F F^T, smem-tiled ----------------
#define GK 4096
#define GC 128
__global__ void gram_kernel(const float* __restrict__ feat) {
    __shared__ float tile[GC][68];
    const int n = blockIdx.y;
    const int base = blockIdx.x * GK;
    const int tid = threadIdx.x;
    const int r0 = (tid / 16) * 4, c0 = (tid % 16) * 4;
    float acc[4][4] = {};
    for (int cb = 0; cb < GK; cb += GC) {
        __syncthreads();
        #pragma unroll
        for (int it = 0; it < 32; it++) {
            int li = it * 256 + tid;
            int ch = li >> 7, k = li & 127;
            tile[k][ch] = feat[(unsigned int)(n*64 + ch) * SS + base + cb + k];
        }
        __syncthreads();
        #pragma unroll 4
        for (int k = 0; k < GC; k++) {
            float4 a  = *(const float4*)&tile[k][r0];
            float4 bq = *(const float4*)&tile[k][c0];
            acc[0][0] = fmaf(a.x, bq.x, acc[0][0]); acc[0][1] = fmaf(a.x, bq.y, acc[0][1]);
            acc[0][2] = fmaf(a.x, bq.z, acc[0][2]); acc[0][3] = fmaf(a.x, bq.w, acc[0][3]);
            acc[1][0] = fmaf(a.y, bq.x, acc[1][0]); acc[1][1] = fmaf(a.y, bq.y, acc[1][1]);
            acc[1][2] = fmaf(a.y, bq.z, acc[1][2]); acc[1][3] = fmaf(a.y, bq.w, acc[1][3]);
            acc[2][0] = fmaf(a.z, bq.x, acc[2][0]); acc[2][1] = fmaf(a.z, bq.y, acc[2][1]);
            acc[2][2] = fmaf(a.z, bq.z, acc[2][2]); acc[2][3] = fmaf(a.z, bq.w, acc[2][3]);
            acc[3][0] = fmaf(a.w, bq.x, acc[3][0]); acc[3][1] = fmaf(a.w, bq.y, acc[3][1]);
            acc[3][2] = fmaf(a.w, bq.z, acc[3][2]); acc[3][3] = fmaf(a.w, bq.w, acc[3][3]);
        }
    }
    #pragma unroll
    for (int i = 0; i < 4; i++)
        #pragma unroll
        for (int j = 0; j < 4; j++)
            atomicAdd(&g_gram[n*4096 + (r0 + i)*64 + c0 + j], acc[i][j]);
}

// ---------------- style loss ----------------
__global__ void style_kernel(const float* __restrict__ tgt) {
    int i = blockIdx.x * 256 + threadIdx.x;
    double d = 0.0;
    if (i < BN*CO*CO) {
        float g = g_gram[i] * (1.0f / ((float)CO * HH * WW));
        float df = g - tgt[i];
        d = (double)df * (double)df;
    }
    block_add(d, &g_accum[1]);
}

// ---------------- finalize ----------------
__global__ void finalize_kernel(float* __restrict__ out) {
    if (threadIdx.x == 0) {
        out[NCS + 0] = (float)(g_accum[0] / (double)NCS);
        out[NCS + 1] = (float)(g_accum[1] / (double)(BN*CO*CO));
        out[NCS + 2] = (float)(g_accum[2] / (double)NCS);
    }
}

// ---------------- launch ----------------
extern "C" void kernel_launch(void* const* d_in, const int* in_sizes, int n_in,
                              void* d_out, int out_size) {
    const float* img  = (const float*)d_in[0];
    const float* w    = (const float*)d_in[1];
    const float* b    = (const float*)d_in[2];
    const float* ct   = (const float*)d_in[3];
    const float* stg  = (const float*)d_in[4];
    const float* hist = (const float*)d_in[5];
    float* out = (float*)d_out;

    void *p_hs, *p_hr, *p_ss, *p_rs;
    cudaGetSymbolAddress(&p_hs, g_hist_src);
    cudaGetSymbolAddress(&p_hr, g_hist_ref);
    cudaGetSymbolAddress(&p_ss, g_src_sorted);
    cudaGetSymbolAddress(&p_rs, g_ref_sorted);

    static int smem_set = 0;
    if (!smem_set) {
        cudaFuncSetAttribute(src_hist_kernel, cudaFuncAttributeMaxDynamicSharedMemorySize, 131072);
        cudaFuncSetAttribute(ref_hist_kernel, cudaFuncAttributeMaxDynamicSharedMemorySize, 131072);
        smem_set = 1;
    }

    init_kernel<<<64, 256>>>();

    dim3 cgrid(WW/32, HH/8, BN), cblk(32, 8);
    conv_kernel<<<cgrid, cblk>>>(img, w, b, ct, out);

    src_hist_kernel<<<NC, 1024, 131072>>>((const float4*)out);
    ref_hist_kernel<<<NC, 1024, 131072>>>((const float4*)hist);

    scan_kernel<<<NC, 1024>>>((unsigned int*)p_hs);
    scan_kernel<<<NC, 1024>>>((unsigned int*)p_hr);

    writeout_kernel<<<dim3(KB/256, NC), 256>>>((const unsigned int*)p_hr, (float*)p_rs, (unsigned int)MM);
    writeout_kernel<<<dim3(KB/256, NC), 256>>>((const unsigned int*)p_hs, (float*)p_ss, (unsigned int)SS);

    gram_kernel<<<dim3(SS/GK, BN), 256>>>(out);
    style_kernel<<<(BN*CO*CO + 255)/256, 256>>>(stg);

    hist_loss_kernel<<<NCS/1024, 256>>>();

    finalize_kernel<<<1, 32>>>(out);
    (void)in_sizes; (void)n_in; (void)out_size;
}